// round 13
// baseline (speedup 1.0000x reference)
#include <cuda_runtime.h>
#include <cuda_bf16.h>
#include <math.h>
#include <stdint.h>

// Problem constants
#define Bdim 64
#define Ldim 80
#define KDET 36
#define DV   256
#define DQ   512
#define Hdim 512
#define NLB  (Ldim*Bdim)     // 5120
#define NROWS (NLB*KDET)     // 184320
#define MAXI  (NLB*5)        // 25600 max 8-row items
#define IPB   16             // items per k_main block
#define NBLK  (MAXI/IPB)     // 1600

// Scratch (__device__ globals: no runtime allocation allowed)
__device__ float          g_sumsq[3];
__device__ __nv_bfloat16  g_Wv[Hdim*DV];
__device__ __nv_bfloat16  g_Wq[Hdim*DQ];
__device__ float          g_u[(size_t)NLB*Hdim];
__device__ float          g_logits[NROWS];
__device__ int            g_items[MAXI];
__device__ int            g_nitems;

// ---------------------------------------------------------------------------
__device__ __forceinline__ unsigned sptr(const void* p) {
    return (unsigned)__cvta_generic_to_shared(p);
}
__device__ __forceinline__ void ldsm4(unsigned* r, unsigned a) {
    asm volatile("ldmatrix.sync.aligned.m8n8.x4.shared.b16 {%0,%1,%2,%3}, [%4];\n"
                 : "=r"(r[0]), "=r"(r[1]), "=r"(r[2]), "=r"(r[3]) : "r"(a));
}
#define CPA16(dst, src) asm volatile("cp.async.cg.shared.global [%0], [%1], 16;\n" :: "r"(dst), "l"(src))
#define CPCOMMIT()      asm volatile("cp.async.commit_group;\n")
#define CPWAIT1()       asm volatile("cp.async.wait_group 1;\n")
#define CPWAIT0()       asm volatile("cp.async.wait_group 0;\n")

__device__ __forceinline__ void mma_bf16(float* c, const unsigned* a, const unsigned* b) {
    asm volatile(
        "mma.sync.aligned.m16n8k16.row.col.f32.bf16.bf16.f32 "
        "{%0,%1,%2,%3}, {%4,%5,%6,%7}, {%8,%9}, {%0,%1,%2,%3};\n"
        : "+f"(c[0]), "+f"(c[1]), "+f"(c[2]), "+f"(c[3])
        : "r"(a[0]), "r"(a[1]), "r"(a[2]), "r"(a[3]), "r"(b[0]), "r"(b[1]));
}

// ---------------------------------------------------------------------------
__global__ void k_zero() {
    int i = blockIdx.x * 256 + threadIdx.x;
    if (i < 3) g_sumsq[i] = 0.f;
    if (i == 3) g_nitems = 0;
    if (i < MAXI) g_items[i] = -1;
}

__global__ void k_items(const int* __restrict__ lengths) {
    int lb = blockIdx.x * 256 + threadIdx.x;
    if (lb >= NLB) return;
    int len = lengths[lb];
    if (len > KDET) len = KDET;
    if (len < 0) len = 0;
    int n8 = (len + 7) >> 3;
    if (n8 == 0) return;
    int pos = atomicAdd(&g_nitems, n8);
    for (int j = 0; j < n8; ++j) g_items[pos + j] = (lb << 3) | j;
}

__global__ void k_sumsq(const float* __restrict__ Vv, const float* __restrict__ Vq,
                        const float* __restrict__ Vl) {
    float sv = 0.f, sq = 0.f, sl = 0.f;
    int stride = gridDim.x * blockDim.x;
    for (int i = blockIdx.x * blockDim.x + threadIdx.x; i < Hdim*DQ; i += stride) {
        float x = Vq[i]; sq += x*x;
        if (i < Hdim*DV) { float y = Vv[i]; sv += y*y; }
        if (i < Hdim)    { float z = Vl[i]; sl += z*z; }
    }
    #pragma unroll
    for (int o = 16; o; o >>= 1) {
        sv += __shfl_xor_sync(~0u, sv, o);
        sq += __shfl_xor_sync(~0u, sq, o);
        sl += __shfl_xor_sync(~0u, sl, o);
    }
    __shared__ float rs[3][8];
    int w = threadIdx.x >> 5;
    if ((threadIdx.x & 31) == 0) { rs[0][w] = sv; rs[1][w] = sq; rs[2][w] = sl; }
    __syncthreads();
    if (threadIdx.x == 0) {
        float a = 0.f, b = 0.f, c = 0.f;
        for (int i = 0; i < 8; ++i) { a += rs[0][i]; b += rs[1][i]; c += rs[2][i]; }
        atomicAdd(&g_sumsq[0], a); atomicAdd(&g_sumsq[1], b); atomicAdd(&g_sumsq[2], c);
    }
}

__global__ void k_convert(const float* __restrict__ Vv, const float* __restrict__ Vq) {
    int i = blockIdx.x * blockDim.x + threadIdx.x;
    if (i < Hdim*DQ) g_Wq[i] = __float2bfloat16(Vq[i]);
    if (i < Hdim*DV) g_Wv[i] = __float2bfloat16(Vv[i]);
}

// ---------------------------------------------------------------------------
// k_u: best-measured variant (33.1 us): grid (80 l, 4 h-slices of 128),
// 256 threads, 137216 B smem, SINGLE W buffer, 2 chunks of 64 h-rows.
#define SU 520
__global__ __launch_bounds__(256, 1)
void k_u(const float* __restrict__ ctx, const float* __restrict__ gq,
         const float* __restrict__ bq, const float* __restrict__ Vl,
         const float* __restrict__ gl) {
    extern __shared__ __align__(16) char sm[];
    __nv_bfloat16* A    = (__nv_bfloat16*)sm;               // 64 x 520 (66560 B)
    __nv_bfloat16* W    = (__nv_bfloat16*)(sm + 66560);     // 64 x 520 (66560 B)
    float*         bq_s = (float*)(sm + 133120);            // 512 f32
    float*         wl_s = (float*)(sm + 135168);            // 512 f32

    const int tid = threadIdx.x;
    const int l   = blockIdx.x;
    const int hbase = blockIdx.y * 128;
    const float s_q = gq[0] * rsqrtf(g_sumsq[1]);
    const float s_l = gl[0] * rsqrtf(g_sumsq[2]);

    for (int i = tid; i < Hdim; i += 256) { bq_s[i] = bq[i]; wl_s[i] = s_l * Vl[i]; }

    {
        const __nv_bfloat16* src = g_Wq + (size_t)hbase * DQ;
        #pragma unroll
        for (int it = 0; it < 16; ++it) {
            int i = tid + it * 256; int r = i >> 6, c8 = i & 63;
            CPA16(sptr(W + r * SU + c8 * 8), src + (size_t)r * DQ + c8 * 8);
        }
        CPCOMMIT();
    }

    #pragma unroll 4
    for (int it = 0; it < 32; ++it) {
        int i  = tid + it * 256;
        int r  = i >> 7, c4 = i & 127;
        float4 f = *(const float4*)(ctx + ((size_t)r * Ldim + l) * DQ + c4 * 4);
        __nv_bfloat16* ap = A + r * SU + c4 * 4;
        *(__nv_bfloat162*)(ap)     = __floats2bfloat162_rn(f.x, f.y);
        *(__nv_bfloat162*)(ap + 2) = __floats2bfloat162_rn(f.z, f.w);
    }

    const int lane = tid & 31, warp = tid >> 5;
    const int wm = warp & 1, wn = warp >> 1;
    const int grp = lane >> 2, lane4 = lane & 3;

    const int aRowL = (lane & 7) + ((lane >> 3) & 1) * 8;
    const int aColL = (lane >> 4) * 8;
    unsigned aAddr[2];
    #pragma unroll
    for (int mf = 0; mf < 2; ++mf)
        aAddr[mf] = sptr(A + (wm*32 + mf*16 + aRowL) * SU + aColL);
    const int bRowL = wn*16 + (lane & 7) + (lane >> 4) * 8;
    const int bColL = ((lane >> 3) & 1) * 8;
    const unsigned bAddr = sptr(W + bRowL * SU + bColL);

    for (int c = 0; c < 2; ++c) {
        CPWAIT0();
        __syncthreads();

        float acc[2][2][4] = {};
        #pragma unroll
        for (int ks = 0; ks < 32; ++ks) {
            unsigned a[2][4], b[4];
            ldsm4(a[0], aAddr[0] + ks*32);
            ldsm4(a[1], aAddr[1] + ks*32);
            ldsm4(b, bAddr + ks*32);
            #pragma unroll
            for (int mf = 0; mf < 2; ++mf) {
                mma_bf16(acc[mf][0], a[mf], b);
                mma_bf16(acc[mf][1], a[mf], b + 2);
            }
        }
        __syncthreads();

        if (c == 0) {
            const __nv_bfloat16* src = g_Wq + (size_t)(hbase + 64) * DQ;
            #pragma unroll
            for (int it = 0; it < 16; ++it) {
                int i = tid + it * 256; int r = i >> 6, c8 = i & 63;
                CPA16(sptr(W + r * SU + c8 * 8), src + (size_t)r * DQ + c8 * 8);
            }
            CPCOMMIT();
        }

        const int h0 = hbase + c*64 + wn*16 + lane4*2;
        #pragma unroll
        for (int mf = 0; mf < 2; ++mf) {
            int r0 = wm*32 + mf*16 + grp, r1 = r0 + 8;
            #pragma unroll
            for (int nf = 0; nf < 2; ++nf) {
                int h = h0 + nf*8;
                float2 o0, o1;
                o0.x = fmaxf(fmaf(s_q, acc[mf][nf][0], bq_s[h]),   0.f) * wl_s[h];
                o0.y = fmaxf(fmaf(s_q, acc[mf][nf][1], bq_s[h+1]), 0.f) * wl_s[h+1];
                o1.x = fmaxf(fmaf(s_q, acc[mf][nf][2], bq_s[h]),   0.f) * wl_s[h];
                o1.y = fmaxf(fmaf(s_q, acc[mf][nf][3], bq_s[h+1]), 0.f) * wl_s[h+1];
                *(float2*)&g_u[(size_t)(l*64 + r0) * Hdim + h] = o0;
                *(float2*)&g_u[(size_t)(l*64 + r1) * Hdim + h] = o1;
            }
        }
    }
}

// ---------------------------------------------------------------------------
// k_main: compacted-work GEMM, 16 items (128 A-rows) per block, u staged in
// SMEM (one 512-f32 row per item). Warps 4M x 2N, pipelined ldsm, double-
// buffered W. Logits scattered to g_logits.
#define SA    264
#define SUU   520          // u_s row stride in f32
#define KM_A   0           // A: 128*264*2        = 67584
#define KM_W   67584       // W: 2*64*264*2       = 67584
#define KM_U   135168      // u_s: 16*520*4       = 33280
#define KM_BV  168448      // bv: 2048
#define KM_LG  170496      // lg: 128*4 = 512
#define KM_IT  171008      // itm: 16*4 = 64
#define KM_SMEM 171072
__global__ __launch_bounds__(256, 1)
void k_main(const float* __restrict__ v, const float* __restrict__ gv,
            const float* __restrict__ bv) {
    extern __shared__ __align__(16) char sm[];
    __nv_bfloat16* A    = (__nv_bfloat16*)(sm + KM_A);
    __nv_bfloat16* W    = (__nv_bfloat16*)(sm + KM_W);
    float*         u_s  = (float*)(sm + KM_U);
    float*         bv_s = (float*)(sm + KM_BV);
    float*         lg   = (float*)(sm + KM_LG);
    int*           itm_s= (int*)(sm + KM_IT);

    const int tid = threadIdx.x;
    const int it0g = blockIdx.x * IPB;
    if (it0g >= g_nitems) return;          // uniform exit for idle blocks
    const float s_v = gv[0] * rsqrtf(g_sumsq[0]);

    // stage items, bv; zero logits
    if (tid < IPB) itm_s[tid] = g_items[it0g + tid];
    if (tid < 128) ((float4*)bv_s)[tid] = ((const float4*)bv)[tid];
    if (tid < 128) lg[tid] = 0.f;

    // prefetch W chunk 0
    {
        #pragma unroll
        for (int it = 0; it < 8; ++it) {
            int i = tid + it * 256; int r = i >> 5, c8 = i & 31;
            CPA16(sptr(W + r * SA + c8 * 8), g_Wv + (size_t)r * DV + c8 * 8);
        }
        CPCOMMIT();
    }
    __syncthreads();                       // itm_s visible

    // stage u rows (one per item) into smem: 16 x 128 float4
    #pragma unroll
    for (int it = 0; it < 8; ++it) {
        int i = tid + it * 256;            // 2048 float4
        int row = i >> 7, c4 = i & 127;
        int m = itm_s[row];
        int lb = (m >= 0) ? (m >> 3) : 0;
        float4 f = *(const float4*)(g_u + (size_t)lb * Hdim + c4 * 4);
        *(float4*)(u_s + row * SUU + c4 * 4) = f;
    }

    // stage A: gather 128 rows (8 per item) of v, f32 -> bf16
    #pragma unroll 4
    for (int it = 0; it < 32; ++it) {
        int i = tid + it * 256;            // 8192 float4
        int r = i >> 6, c4 = i & 63;
        int m = itm_s[r >> 3];
        if (m >= 0) {
            int k = ((m & 7) << 3) + (r & 7);
            if (k < KDET) {
                float4 f = *(const float4*)(v + ((size_t)(m >> 3) * KDET + k) * DV + c4 * 4);
                __nv_bfloat16* ap = A + r * SA + c4 * 4;
                *(__nv_bfloat162*)(ap)     = __floats2bfloat162_rn(f.x, f.y);
                *(__nv_bfloat162*)(ap + 2) = __floats2bfloat162_rn(f.z, f.w);
            }
        }
    }

    const int lane = tid & 31, warp = tid >> 5;
    const int wm = warp & 3, wn = warp >> 2;      // 4 warps M(128), 2 warps N(64)
    const int grp = lane >> 2, lane4 = lane & 3;

    const int aRowL = (lane & 7) + ((lane >> 3) & 1) * 8;
    const int aColL = (lane >> 4) * 8;
    unsigned aAddr[2];
    #pragma unroll
    for (int mf = 0; mf < 2; ++mf)
        aAddr[mf] = sptr(A + (wm*32 + mf*16 + aRowL) * SA + aColL);
    const int bRowL = wn*32 + (lane & 7) + (lane >> 4) * 8;
    const int bColL = ((lane >> 3) & 1) * 8;
    unsigned bAddrBase[2];
    bAddrBase[0] = sptr(W + bRowL * SA + bColL);
    bAddrBase[1] = sptr(W + 64*SA + bRowL * SA + bColL);
    const unsigned bOff16 = 16 * SA * 2;

    // per-m-tile row halves -> item slots
    int r0v[2], r1v[2], iu0[2], iu1[2];
    bool ok0[2], ok1[2];
    #pragma unroll
    for (int mf = 0; mf < 2; ++mf) {
        int iti = wm*4 + mf*2;
        ok0[mf] = itm_s[iti]     >= 0;
        ok1[mf] = itm_s[iti + 1] >= 0;
        iu0[mf] = iti * SUU; iu1[mf] = (iti + 1) * SUU;
        r0v[mf] = wm*32 + mf*16 + grp; r1v[mf] = r0v[mf] + 8;
    }
    float part0[2] = {0,0}, part1[2] = {0,0};

    for (int c = 0; c < 8; ++c) {
        if (c < 7) {
            const __nv_bfloat16* src = g_Wv + (size_t)(c+1) * 64 * DV;
            __nv_bfloat16* dst = W + ((c+1) & 1) * 64 * SA;
            #pragma unroll
            for (int it = 0; it < 8; ++it) {
                int i = tid + it * 256; int r = i >> 5, c8 = i & 31;
                CPA16(sptr(dst + r * SA + c8 * 8), src + (size_t)r * DV + c8 * 8);
            }
            CPCOMMIT();
            CPWAIT1();
        } else {
            CPWAIT0();
        }
        __syncthreads();

        // pipelined mainloop over K=256 (16 k16 steps)
        float acc[2][4][4] = {};
        const unsigned bB = bAddrBase[c & 1];
        unsigned aF[2][2][4], bF[2][8];
        ldsm4(aF[0][0], aAddr[0]);
        ldsm4(aF[0][1], aAddr[1]);
        ldsm4(bF[0],     bB);
        ldsm4(bF[0] + 4, bB + bOff16);
        #pragma unroll
        for (int ks = 0; ks < 16; ++ks) {
            const int cur = ks & 1, nxt = cur ^ 1;
            if (ks < 15) {
                const unsigned off = (unsigned)(ks + 1) * 32;
                ldsm4(aF[nxt][0], aAddr[0] + off);
                ldsm4(aF[nxt][1], aAddr[1] + off);
                ldsm4(bF[nxt],     bB + off);
                ldsm4(bF[nxt] + 4, bB + bOff16 + off);
            }
            #pragma unroll
            for (int mf = 0; mf < 2; ++mf)
                #pragma unroll
                for (int nf = 0; nf < 4; ++nf)
                    mma_bf16(acc[mf][nf], aF[cur][mf], bF[cur] + nf*2);
        }

        // epilogue partial: relu-dot with u (broadcast LDS)
        const int hb = c*64 + wn*32 + lane4*2;
        #pragma unroll
        for (int mf = 0; mf < 2; ++mf) {
            float slo = 0.f, shi = 0.f;
            #pragma unroll
            for (int nf = 0; nf < 4; ++nf) {
                int h = hb + nf*8;
                float b0 = bv_s[h], b1 = bv_s[h+1];
                float2 u0 = *(const float2*)(u_s + iu0[mf] + h);
                float2 u1 = *(const float2*)(u_s + iu1[mf] + h);
                slo += fmaxf(fmaf(s_v, acc[mf][nf][0], b0), 0.f) * u0.x
                     + fmaxf(fmaf(s_v, acc[mf][nf][1], b1), 0.f) * u0.y;
                shi += fmaxf(fmaf(s_v, acc[mf][nf][2], b0), 0.f) * u1.x
                     + fmaxf(fmaf(s_v, acc[mf][nf][3], b1), 0.f) * u1.y;
            }
            part0[mf] += slo; part1[mf] += shi;
        }
        __syncthreads();
    }

    // quad reduce -> lg (cross-wn via smem atomics)
    #pragma unroll
    for (int mf = 0; mf < 2; ++mf) {
        float slo = part0[mf], shi = part1[mf];
        slo += __shfl_xor_sync(~0u, slo, 1); slo += __shfl_xor_sync(~0u, slo, 2);
        shi += __shfl_xor_sync(~0u, shi, 1); shi += __shfl_xor_sync(~0u, shi, 2);
        if (lane4 == 0) {
            if (ok0[mf]) atomicAdd(&lg[r0v[mf]], slo);
            if (ok1[mf]) atomicAdd(&lg[r1v[mf]], shi);
        }
    }
    __syncthreads();

    // scatter logits
    if (tid < 128) {
        int m = itm_s[tid >> 3];
        if (m >= 0) {
            int k = ((m & 7) << 3) + (tid & 7);
            if (k < KDET) g_logits[(m >> 3) * KDET + k] = lg[tid];
        }
    }
}

// ---------------------------------------------------------------------------
// k_out: per lb, softmax over valid k + fp32 weighted sum of v -> out [B,L,Dv]
__global__ __launch_bounds__(128)
void k_out(const float* __restrict__ v, const int* __restrict__ lengths,
           float* __restrict__ out) {
    __shared__ float w_s[KDET];
    __shared__ int len_sh;
    const int lb = blockIdx.x;
    const int tid = threadIdx.x;

    if (tid < KDET) w_s[tid] = g_logits[lb * KDET + tid];
    __syncthreads();
    if (tid == 0) {
        int len = lengths[lb];
        if (len > KDET) len = KDET;
        if (len < 0) len = 0;
        len_sh = len;
        if (len > 0) {
            float m = -1e30f;
            for (int k = 0; k < len; ++k) m = fmaxf(m, w_s[k]);
            float s = 0.f;
            for (int k = 0; k < len; ++k) { float e = __expf(w_s[k] - m); w_s[k] = e; s += e; }
            float inv = 1.f / s;
            for (int k = 0; k < len; ++k) w_s[k] *= inv;
        }
    }
    __syncthreads();

    const int len = len_sh;
    const float* vr = v + (size_t)lb * KDET * DV + tid * 2;
    float ax = 0.f, ay = 0.f;
    #pragma unroll 4
    for (int k = 0; k < len; ++k) {
        float wgt = w_s[k];
        float2 x = *(const float2*)(vr + (size_t)k * DV);
        ax = fmaf(wgt, x.x, ax);
        ay = fmaf(wgt, x.y, ay);
    }
    const int l = lb >> 6, bb = lb & 63;
    float2 o; o.x = ax; o.y = ay;
    *(float2*)(out + ((size_t)bb * Ldim + l) * DV + tid * 2) = o;
}

// ---------------------------------------------------------------------------
extern "C" void kernel_launch(void* const* d_in, const int* in_sizes, int n_in,
                              void* d_out, int out_size) {
    const float* ctx     = (const float*)d_in[0];
    const float* v       = (const float*)d_in[1];
    const int*   lengths = (const int*)  d_in[2];
    const float* Vv      = (const float*)d_in[3];
    const float* gv      = (const float*)d_in[4];
    const float* bvp     = (const float*)d_in[5];
    const float* Vq      = (const float*)d_in[6];
    const float* gq      = (const float*)d_in[7];
    const float* bq      = (const float*)d_in[8];
    const float* Vl      = (const float*)d_in[9];
    const float* gl      = (const float*)d_in[10];
    // d_in[11] = bl: constant logit shift, cancels in softmax.
    (void)in_sizes; (void)n_in; (void)out_size;

    cudaFuncSetAttribute(k_u,    cudaFuncAttributeMaxDynamicSharedMemorySize, 137216);
    cudaFuncSetAttribute(k_main, cudaFuncAttributeMaxDynamicSharedMemorySize, KM_SMEM);

    k_zero<<<101, 256>>>();
    k_items<<<20, 256>>>(lengths);
    k_sumsq<<<128, 256>>>(Vv, Vq, Vl);
    k_convert<<<(Hdim*DQ + 255) / 256, 256>>>(Vv, Vq);
    dim3 gu(Ldim, 4);
    k_u<<<gu, 256, 137216>>>(ctx, gq, bq, Vl, gl);
    k_main<<<NBLK, 256, KM_SMEM>>>(v, gv, bvp);
    k_out<<<NLB, 128>>>(v, lengths, (float*)d_out);
}

// round 14
// speedup vs baseline: 1.2371x; 1.2371x over previous
#include <cuda_runtime.h>
#include <cuda_bf16.h>
#include <math.h>
#include <stdint.h>

// Problem constants
#define Bdim 64
#define Ldim 80
#define KDET 36
#define DV   256
#define DQ   512
#define Hdim 512
#define NLB  (Ldim*Bdim)     // 5120
#define NROWS (NLB*KDET)     // 184320
#define MAXI  (NLB*5)        // 25600 max 8-row items
#define IPB   12             // items per k_main block
#define NBLK  2134           // ceil(25600/12)
#define MAXIP (NBLK*IPB)     // 25608 (padded)

// Scratch (__device__ globals: no runtime allocation allowed)
__device__ float          g_sumsq[3];
__device__ __nv_bfloat16  g_Wv[Hdim*DV];
__device__ __nv_bfloat16  g_Wq[Hdim*DQ];
__device__ float          g_u[(size_t)NLB*Hdim];
__device__ float          g_logits[NROWS];
__device__ int            g_items[MAXIP];
__device__ int            g_nitems;

// ---------------------------------------------------------------------------
__device__ __forceinline__ unsigned sptr(const void* p) {
    return (unsigned)__cvta_generic_to_shared(p);
}
__device__ __forceinline__ void ldsm4(unsigned* r, unsigned a) {
    asm volatile("ldmatrix.sync.aligned.m8n8.x4.shared.b16 {%0,%1,%2,%3}, [%4];\n"
                 : "=r"(r[0]), "=r"(r[1]), "=r"(r[2]), "=r"(r[3]) : "r"(a));
}
#define CPA16(dst, src) asm volatile("cp.async.cg.shared.global [%0], [%1], 16;\n" :: "r"(dst), "l"(src))
#define CPCOMMIT()      asm volatile("cp.async.commit_group;\n")
#define CPWAIT0()       asm volatile("cp.async.wait_group 0;\n")

__device__ __forceinline__ void mma_bf16(float* c, const unsigned* a, const unsigned* b) {
    asm volatile(
        "mma.sync.aligned.m16n8k16.row.col.f32.bf16.bf16.f32 "
        "{%0,%1,%2,%3}, {%4,%5,%6,%7}, {%8,%9}, {%0,%1,%2,%3};\n"
        : "+f"(c[0]), "+f"(c[1]), "+f"(c[2]), "+f"(c[3])
        : "r"(a[0]), "r"(a[1]), "r"(a[2]), "r"(a[3]), "r"(b[0]), "r"(b[1]));
}

// ---------------------------------------------------------------------------
__global__ void k_zero() {
    int i = blockIdx.x * 256 + threadIdx.x;
    if (i < 3) g_sumsq[i] = 0.f;
    if (i == 3) g_nitems = 0;
    if (i < MAXIP) g_items[i] = -1;
}

__global__ void k_items(const int* __restrict__ lengths) {
    int lb = blockIdx.x * 256 + threadIdx.x;
    if (lb >= NLB) return;
    int len = lengths[lb];
    if (len > KDET) len = KDET;
    if (len < 0) len = 0;
    int n8 = (len + 7) >> 3;
    if (n8 == 0) return;
    int pos = atomicAdd(&g_nitems, n8);
    for (int j = 0; j < n8; ++j) g_items[pos + j] = (lb << 3) | j;
}

__global__ void k_sumsq(const float* __restrict__ Vv, const float* __restrict__ Vq,
                        const float* __restrict__ Vl) {
    float sv = 0.f, sq = 0.f, sl = 0.f;
    int stride = gridDim.x * blockDim.x;
    for (int i = blockIdx.x * blockDim.x + threadIdx.x; i < Hdim*DQ; i += stride) {
        float x = Vq[i]; sq += x*x;
        if (i < Hdim*DV) { float y = Vv[i]; sv += y*y; }
        if (i < Hdim)    { float z = Vl[i]; sl += z*z; }
    }
    #pragma unroll
    for (int o = 16; o; o >>= 1) {
        sv += __shfl_xor_sync(~0u, sv, o);
        sq += __shfl_xor_sync(~0u, sq, o);
        sl += __shfl_xor_sync(~0u, sl, o);
    }
    __shared__ float rs[3][8];
    int w = threadIdx.x >> 5;
    if ((threadIdx.x & 31) == 0) { rs[0][w] = sv; rs[1][w] = sq; rs[2][w] = sl; }
    __syncthreads();
    if (threadIdx.x == 0) {
        float a = 0.f, b = 0.f, c = 0.f;
        for (int i = 0; i < 8; ++i) { a += rs[0][i]; b += rs[1][i]; c += rs[2][i]; }
        atomicAdd(&g_sumsq[0], a); atomicAdd(&g_sumsq[1], b); atomicAdd(&g_sumsq[2], c);
    }
}

__global__ void k_convert(const float* __restrict__ Vv, const float* __restrict__ Vq) {
    int i = blockIdx.x * blockDim.x + threadIdx.x;
    if (i < Hdim*DQ) g_Wq[i] = __float2bfloat16(Vq[i]);
    if (i < Hdim*DV) g_Wv[i] = __float2bfloat16(Vv[i]);
}

// ---------------------------------------------------------------------------
// k_u: best-measured variant (33.1 us): grid (80 l, 4 h-slices of 128),
// 256 threads, 137216 B smem, SINGLE W buffer, 2 chunks of 64 h-rows.
#define SU 520
__global__ __launch_bounds__(256, 1)
void k_u(const float* __restrict__ ctx, const float* __restrict__ gq,
         const float* __restrict__ bq, const float* __restrict__ Vl,
         const float* __restrict__ gl) {
    extern __shared__ __align__(16) char sm[];
    __nv_bfloat16* A    = (__nv_bfloat16*)sm;               // 64 x 520 (66560 B)
    __nv_bfloat16* W    = (__nv_bfloat16*)(sm + 66560);     // 64 x 520 (66560 B)
    float*         bq_s = (float*)(sm + 133120);            // 512 f32
    float*         wl_s = (float*)(sm + 135168);            // 512 f32

    const int tid = threadIdx.x;
    const int l   = blockIdx.x;
    const int hbase = blockIdx.y * 128;
    const float s_q = gq[0] * rsqrtf(g_sumsq[1]);
    const float s_l = gl[0] * rsqrtf(g_sumsq[2]);

    for (int i = tid; i < Hdim; i += 256) { bq_s[i] = bq[i]; wl_s[i] = s_l * Vl[i]; }

    {
        const __nv_bfloat16* src = g_Wq + (size_t)hbase * DQ;
        #pragma unroll
        for (int it = 0; it < 16; ++it) {
            int i = tid + it * 256; int r = i >> 6, c8 = i & 63;
            CPA16(sptr(W + r * SU + c8 * 8), src + (size_t)r * DQ + c8 * 8);
        }
        CPCOMMIT();
    }

    #pragma unroll 4
    for (int it = 0; it < 32; ++it) {
        int i  = tid + it * 256;
        int r  = i >> 7, c4 = i & 127;
        float4 f = *(const float4*)(ctx + ((size_t)r * Ldim + l) * DQ + c4 * 4);
        __nv_bfloat16* ap = A + r * SU + c4 * 4;
        *(__nv_bfloat162*)(ap)     = __floats2bfloat162_rn(f.x, f.y);
        *(__nv_bfloat162*)(ap + 2) = __floats2bfloat162_rn(f.z, f.w);
    }

    const int lane = tid & 31, warp = tid >> 5;
    const int wm = warp & 1, wn = warp >> 1;
    const int grp = lane >> 2, lane4 = lane & 3;

    const int aRowL = (lane & 7) + ((lane >> 3) & 1) * 8;
    const int aColL = (lane >> 4) * 8;
    unsigned aAddr[2];
    #pragma unroll
    for (int mf = 0; mf < 2; ++mf)
        aAddr[mf] = sptr(A + (wm*32 + mf*16 + aRowL) * SU + aColL);
    const int bRowL = wn*16 + (lane & 7) + (lane >> 4) * 8;
    const int bColL = ((lane >> 3) & 1) * 8;
    const unsigned bAddr = sptr(W + bRowL * SU + bColL);

    for (int c = 0; c < 2; ++c) {
        CPWAIT0();
        __syncthreads();

        float acc[2][2][4] = {};
        #pragma unroll
        for (int ks = 0; ks < 32; ++ks) {
            unsigned a[2][4], b[4];
            ldsm4(a[0], aAddr[0] + ks*32);
            ldsm4(a[1], aAddr[1] + ks*32);
            ldsm4(b, bAddr + ks*32);
            #pragma unroll
            for (int mf = 0; mf < 2; ++mf) {
                mma_bf16(acc[mf][0], a[mf], b);
                mma_bf16(acc[mf][1], a[mf], b + 2);
            }
        }
        __syncthreads();

        if (c == 0) {
            const __nv_bfloat16* src = g_Wq + (size_t)(hbase + 64) * DQ;
            #pragma unroll
            for (int it = 0; it < 16; ++it) {
                int i = tid + it * 256; int r = i >> 6, c8 = i & 63;
                CPA16(sptr(W + r * SU + c8 * 8), src + (size_t)r * DQ + c8 * 8);
            }
            CPCOMMIT();
        }

        const int h0 = hbase + c*64 + wn*16 + lane4*2;
        #pragma unroll
        for (int mf = 0; mf < 2; ++mf) {
            int r0 = wm*32 + mf*16 + grp, r1 = r0 + 8;
            #pragma unroll
            for (int nf = 0; nf < 2; ++nf) {
                int h = h0 + nf*8;
                float2 o0, o1;
                o0.x = fmaxf(fmaf(s_q, acc[mf][nf][0], bq_s[h]),   0.f) * wl_s[h];
                o0.y = fmaxf(fmaf(s_q, acc[mf][nf][1], bq_s[h+1]), 0.f) * wl_s[h+1];
                o1.x = fmaxf(fmaf(s_q, acc[mf][nf][2], bq_s[h]),   0.f) * wl_s[h];
                o1.y = fmaxf(fmaf(s_q, acc[mf][nf][3], bq_s[h+1]), 0.f) * wl_s[h+1];
                *(float2*)&g_u[(size_t)(l*64 + r0) * Hdim + h] = o0;
                *(float2*)&g_u[(size_t)(l*64 + r1) * Hdim + h] = o1;
            }
        }
    }
}

// ---------------------------------------------------------------------------
// k_main: compacted-work GEMM at occupancy 2. 12 items (96 A-rows) per
// block, 86960 B smem -> 2 independent blocks/SM hide each other's stalls.
// Warps 2M x 4N (mf=3, nf=2), pipelined ldsm, single-buffered 64-row W
// chunks (next-chunk DMA overlaps epilogue + co-resident block's compute).
// u read from L2 in epilogue. Logits scattered to g_logits.
#define SA    264
#define KM_A   0           // A: 96*264*2  = 50688
#define KM_W   50688       // W: 64*264*2  = 33792
#define KM_BV  84480       // bv: 2048
#define KM_LG  86528       // lg: 96*4 = 384
#define KM_IT  86912       // itm: 12*4 = 48
#define KM_SMEM 86960
__global__ __launch_bounds__(256, 2)
void k_main(const float* __restrict__ v, const float* __restrict__ gv,
            const float* __restrict__ bv) {
    extern __shared__ __align__(16) char sm[];
    __nv_bfloat16* A    = (__nv_bfloat16*)(sm + KM_A);
    __nv_bfloat16* W    = (__nv_bfloat16*)(sm + KM_W);
    float*         bv_s = (float*)(sm + KM_BV);
    float*         lg   = (float*)(sm + KM_LG);
    int*           itm_s= (int*)(sm + KM_IT);

    const int tid = threadIdx.x;
    const int it0g = blockIdx.x * IPB;
    if (it0g >= g_nitems) return;          // uniform exit for idle blocks
    const float s_v = gv[0] * rsqrtf(g_sumsq[0]);

    // stage items, bv; zero logits
    if (tid < IPB) itm_s[tid] = g_items[it0g + tid];
    if (tid < 128) ((float4*)bv_s)[tid] = ((const float4*)bv)[tid];
    if (tid < 96)  lg[tid] = 0.f;

    // prefetch W chunk 0
    {
        #pragma unroll
        for (int it = 0; it < 8; ++it) {
            int i = tid + it * 256; int r = i >> 5, c8 = i & 31;
            CPA16(sptr(W + r * SA + c8 * 8), g_Wv + (size_t)r * DV + c8 * 8);
        }
        CPCOMMIT();
    }
    __syncthreads();                       // itm_s visible

    // stage A: gather 96 rows (8 per item) of v, f32 -> bf16
    #pragma unroll 4
    for (int it = 0; it < 24; ++it) {
        int i = tid + it * 256;            // 6144 float4
        int r = i >> 6, c4 = i & 63;
        int m = itm_s[r >> 3];
        if (m >= 0) {
            int k = ((m & 7) << 3) + (r & 7);
            if (k < KDET) {
                float4 f = *(const float4*)(v + ((size_t)(m >> 3) * KDET + k) * DV + c4 * 4);
                __nv_bfloat16* ap = A + r * SA + c4 * 4;
                *(__nv_bfloat162*)(ap)     = __floats2bfloat162_rn(f.x, f.y);
                *(__nv_bfloat162*)(ap + 2) = __floats2bfloat162_rn(f.z, f.w);
            }
        }
    }

    const int lane = tid & 31, warp = tid >> 5;
    const int wm = warp & 1, wn = warp >> 1;      // 2 warps M(96), 4 warps N(64)
    const int grp = lane >> 2, lane4 = lane & 3;

    const int aRowL = (lane & 7) + ((lane >> 3) & 1) * 8;
    const int aColL = (lane >> 4) * 8;
    unsigned aAddr[3];
    #pragma unroll
    for (int mf = 0; mf < 3; ++mf)
        aAddr[mf] = sptr(A + (wm*48 + mf*16 + aRowL) * SA + aColL);
    const int bRowL = wn*16 + (lane & 7) + (lane >> 4) * 8;
    const int bColL = ((lane >> 3) & 1) * 8;
    const unsigned bAddr = sptr(W + bRowL * SA + bColL);

    // per-m-tile row halves -> items -> u row pointers (L2)
    int r0v[3], r1v[3];
    bool ok0[3], ok1[3];
    const float* up0[3];
    const float* up1[3];
    #pragma unroll
    for (int mf = 0; mf < 3; ++mf) {
        int iti = wm*6 + mf*2;
        int m0 = itm_s[iti], m1 = itm_s[iti + 1];
        ok0[mf] = m0 >= 0; ok1[mf] = m1 >= 0;
        up0[mf] = g_u + (size_t)((ok0[mf] ? m0 : 0) >> 3) * Hdim;
        up1[mf] = g_u + (size_t)((ok1[mf] ? m1 : 0) >> 3) * Hdim;
        r0v[mf] = wm*48 + mf*16 + grp; r1v[mf] = r0v[mf] + 8;
    }
    float part0[3] = {0,0,0}, part1[3] = {0,0,0};

    for (int c = 0; c < 8; ++c) {
        CPWAIT0();
        __syncthreads();

        // pipelined mainloop over K=256 (16 k16 steps)
        float acc[3][2][4] = {};
        unsigned aF[2][3][4], bF[2][4];
        ldsm4(aF[0][0], aAddr[0]);
        ldsm4(aF[0][1], aAddr[1]);
        ldsm4(aF[0][2], aAddr[2]);
        ldsm4(bF[0], bAddr);
        #pragma unroll
        for (int ks = 0; ks < 16; ++ks) {
            const int cur = ks & 1, nxt = cur ^ 1;
            if (ks < 15) {
                const unsigned off = (unsigned)(ks + 1) * 32;
                ldsm4(aF[nxt][0], aAddr[0] + off);
                ldsm4(aF[nxt][1], aAddr[1] + off);
                ldsm4(aF[nxt][2], aAddr[2] + off);
                ldsm4(bF[nxt], bAddr + off);
            }
            #pragma unroll
            for (int mf = 0; mf < 3; ++mf) {
                mma_bf16(acc[mf][0], aF[cur][mf], bF[cur]);
                mma_bf16(acc[mf][1], aF[cur][mf], bF[cur] + 2);
            }
        }
        __syncthreads();   // all warps done reading W before refill

        if (c < 7) {       // next W chunk; DMA overlaps epilogue below
            const __nv_bfloat16* src = g_Wv + (size_t)(c+1) * 64 * DV;
            #pragma unroll
            for (int it = 0; it < 8; ++it) {
                int i = tid + it * 256; int r = i >> 5, c8 = i & 31;
                CPA16(sptr(W + r * SA + c8 * 8), src + (size_t)r * DV + c8 * 8);
            }
            CPCOMMIT();
        }

        // epilogue partial: relu-dot with u (L2 broadcast loads)
        const int hb = c*64 + wn*16 + lane4*2;
        #pragma unroll
        for (int mf = 0; mf < 3; ++mf) {
            float slo = 0.f, shi = 0.f;
            #pragma unroll
            for (int nf = 0; nf < 2; ++nf) {
                int h = hb + nf*8;
                float b0 = bv_s[h], b1 = bv_s[h+1];
                float2 u0 = *(const float2*)(up0[mf] + h);
                float2 u1 = *(const float2*)(up1[mf] + h);
                slo += fmaxf(fmaf(s_v, acc[mf][nf][0], b0), 0.f) * u0.x
                     + fmaxf(fmaf(s_v, acc[mf][nf][1], b1), 0.f) * u0.y;
                shi += fmaxf(fmaf(s_v, acc[mf][nf][2], b0), 0.f) * u1.x
                     + fmaxf(fmaf(s_v, acc[mf][nf][3], b1), 0.f) * u1.y;
            }
            part0[mf] += slo; part1[mf] += shi;
        }
    }

    // quad reduce -> lg (cross-wn via smem atomics)
    #pragma unroll
    for (int mf = 0; mf < 3; ++mf) {
        float slo = part0[mf], shi = part1[mf];
        slo += __shfl_xor_sync(~0u, slo, 1); slo += __shfl_xor_sync(~0u, slo, 2);
        shi += __shfl_xor_sync(~0u, shi, 1); shi += __shfl_xor_sync(~0u, shi, 2);
        if (lane4 == 0) {
            if (ok0[mf]) atomicAdd(&lg[r0v[mf]], slo);
            if (ok1[mf]) atomicAdd(&lg[r1v[mf]], shi);
        }
    }
    __syncthreads();

    // scatter logits
    if (tid < 96) {
        int m = itm_s[tid >> 3];
        if (m >= 0) {
            int k = ((m & 7) << 3) + (tid & 7);
            if (k < KDET) g_logits[(m >> 3) * KDET + k] = lg[tid];
        }
    }
}

// ---------------------------------------------------------------------------
// k_out: per lb, softmax over valid k + fp32 weighted sum of v -> out [B,L,Dv]
__global__ __launch_bounds__(128)
void k_out(const float* __restrict__ v, const int* __restrict__ lengths,
           float* __restrict__ out) {
    __shared__ float w_s[KDET];
    __shared__ int len_sh;
    const int lb = blockIdx.x;
    const int tid = threadIdx.x;

    if (tid < KDET) w_s[tid] = g_logits[lb * KDET + tid];
    __syncthreads();
    if (tid == 0) {
        int len = lengths[lb];
        if (len > KDET) len = KDET;
        if (len < 0) len = 0;
        len_sh = len;
        if (len > 0) {
            float m = -1e30f;
            for (int k = 0; k < len; ++k) m = fmaxf(m, w_s[k]);
            float s = 0.f;
            for (int k = 0; k < len; ++k) { float e = __expf(w_s[k] - m); w_s[k] = e; s += e; }
            float inv = 1.f / s;
            for (int k = 0; k < len; ++k) w_s[k] *= inv;
        }
    }
    __syncthreads();

    const int len = len_sh;
    const float* vr = v + (size_t)lb * KDET * DV + tid * 2;
    float ax = 0.f, ay = 0.f;
    #pragma unroll 4
    for (int k = 0; k < len; ++k) {
        float wgt = w_s[k];
        float2 x = *(const float2*)(vr + (size_t)k * DV);
        ax = fmaf(wgt, x.x, ax);
        ay = fmaf(wgt, x.y, ay);
    }
    const int l = lb >> 6, bb = lb & 63;
    float2 o; o.x = ax; o.y = ay;
    *(float2*)(out + ((size_t)bb * Ldim + l) * DV + tid * 2) = o;
}

// ---------------------------------------------------------------------------
extern "C" void kernel_launch(void* const* d_in, const int* in_sizes, int n_in,
                              void* d_out, int out_size) {
    const float* ctx     = (const float*)d_in[0];
    const float* v       = (const float*)d_in[1];
    const int*   lengths = (const int*)  d_in[2];
    const float* Vv      = (const float*)d_in[3];
    const float* gv      = (const float*)d_in[4];
    const float* bvp     = (const float*)d_in[5];
    const float* Vq      = (const float*)d_in[6];
    const float* gq      = (const float*)d_in[7];
    const float* bq      = (const float*)d_in[8];
    const float* Vl      = (const float*)d_in[9];
    const float* gl      = (const float*)d_in[10];
    // d_in[11] = bl: constant logit shift, cancels in softmax.
    (void)in_sizes; (void)n_in; (void)out_size;

    cudaFuncSetAttribute(k_u,    cudaFuncAttributeMaxDynamicSharedMemorySize, 137216);
    cudaFuncSetAttribute(k_main, cudaFuncAttributeMaxDynamicSharedMemorySize, KM_SMEM);

    k_zero<<<101, 256>>>();
    k_items<<<20, 256>>>(lengths);
    k_sumsq<<<128, 256>>>(Vv, Vq, Vl);
    k_convert<<<(Hdim*DQ + 255) / 256, 256>>>(Vv, Vq);
    dim3 gu(Ldim, 4);
    k_u<<<gu, 256, 137216>>>(ctx, gq, bq, Vl, gl);
    k_main<<<NBLK, 256, KM_SMEM>>>(v, gv, bvp);
    k_out<<<NLB, 128>>>(v, lengths, (float*)d_out);
}